// round 6
// baseline (speedup 1.0000x reference)
#include <cuda_runtime.h>

#define BB 1024
#define DD 256
#define HH 32

// exp(+W)/exp(-W), interleaved by j-pair: float2 element [pr*DD + d] holds
// (exp(s*W[d, 2*pr]), exp(s*W[d, 2*pr+1])) -> one coalesced LDG.64 per 2 factors.
__device__ float  g_ewp[HH * DD];
__device__ float  g_ewm[HH * DD];
__device__ float2 g_eb[DD];          // (exp(+b/2), exp(-b/2))
__device__ float  g_E[BB * HH];      // E_j(row) = exp((x@W)_j + c_j)

// One prep kernel: blocks 0..7 build tables, blocks 8..135 compute E (8 rows each).
__global__ __launch_bounds__(256) void prep_kernel(
    const float* __restrict__ x,
    const float* __restrict__ W,
    const float* __restrict__ b,
    const float* __restrict__ c)
{
    const int bid = blockIdx.x;
    const int tid = threadIdx.x;
    if (bid < 8) {
        for (int t = bid * 256 + tid; t < DD * HH; t += 8 * 256) {
            int d = t >> 5;
            int j = t & 31;
            float w = W[t];
            int idx = (j >> 1) * (DD * 2) + d * 2 + (j & 1);
            g_ewp[idx] = expf(w);
            g_ewm[idx] = expf(-w);
        }
        int t = bid * 256 + tid;
        if (t < DD) {
            float bv = b[t];
            g_eb[t] = make_float2(expf(0.5f * bv), expf(-0.5f * bv));
        }
    } else {
        const int w    = tid >> 5;
        const int lane = tid & 31;
        const int row  = (bid - 8) * 8 + w;      // warp = row
        // gather x bits for this row: 8 ballots
        unsigned msk[8];
        #pragma unroll
        for (int m = 0; m < 8; ++m)
            msk[m] = __ballot_sync(0xffffffffu, x[row * DD + m * 32 + lane] != 0.0f);
        float a = c[lane];
        const float* Wp = W + lane;              // W[d*HH + lane], coalesced per d
        #pragma unroll
        for (int m = 0; m < 8; ++m) {
            #pragma unroll
            for (int i = 0; i < 32; ++i)
                if (msk[m] & (1u << i)) a += Wp[(m * 32 + i) * HH];
        }
        g_E[row * HH + lane] = expf(a);
    }
}

__device__ __forceinline__ unsigned fmono(float f) {
    unsigned u = __float_as_uint(f);
    return (u & 0x80000000u) ? ~u : (u | 0x80000000u);
}

__global__ __launch_bounds__(128, 8) void gwg_kernel(
    const float* __restrict__ x,
    const float* __restrict__ gum,
    const float* __restrict__ acc,
    float* __restrict__ out)
{
    __shared__ float xs[DD];
    __shared__ __align__(16) float sEf[HH];   // E_j
    __shared__ __align__(16) float sE2[HH];   // E'_j after rank-1 update
    __shared__ float sredf[4];
    __shared__ uint2 sredk[4];                // (fmono(key), idx) per warp
    __shared__ float sRt;

    const int row  = blockIdx.x;
    const int tid  = threadIdx.x;
    const int w    = tid >> 5;
    const int lane = tid & 31;
    const int k0   = tid;          // dims tid and tid+128
    const int k1   = tid + 128;

    float  xk0 = x[row * DD + k0];
    float  xk1 = x[row * DD + k1];
    float2 eb0 = g_eb[k0];
    float2 eb1 = g_eb[k1];
    float  u0  = gum[row * DD + k0];
    float  u1  = gum[row * DD + k1];
    float  au  = acc[row];
    xs[k0] = xk0;
    xs[k1] = xk1;

    float E = 0.f;                             // warp 0 keeps its E_lane
    if (w == 0) { E = g_E[row * HH + lane]; sEf[lane] = E; }
    __syncthreads();                           // B1

    // ---- forward: p~_k = prod_j (1 + E_j e^{delta_k w_kj});  ek = eb * sqrt ----
    const float2* t0 = (const float2*)((xk0 == 0.0f) ? g_ewp : g_ewm);
    const float2* t1 = (const float2*)((xk1 == 0.0f) ? g_ewp : g_ewm);
    const float ebf0 = (xk0 == 0.0f) ? eb0.x : eb0.y;
    const float ebf1 = (xk1 == 0.0f) ? eb1.x : eb1.y;
    const float4* sE4f = (const float4*)sEf;

    float p0 = 1.f, p1 = 1.f, p2 = 1.f, p3 = 1.f;
    float r0 = 1.f, r1 = 1.f, r2 = 1.f, r3 = 1.f;
    #pragma unroll
    for (int jp = 0; jp < 16; jp += 2) {
        float4 Ev = sE4f[jp >> 1];
        float2 aA = __ldg(&t0[jp * DD + k0]);
        float2 aB = __ldg(&t0[(jp + 1) * DD + k0]);
        float2 bA = __ldg(&t1[jp * DD + k1]);
        float2 bB = __ldg(&t1[(jp + 1) * DD + k1]);
        p0 *= fmaf(Ev.x, aA.x, 1.f);
        p1 *= fmaf(Ev.y, aA.y, 1.f);
        p2 *= fmaf(Ev.z, aB.x, 1.f);
        p3 *= fmaf(Ev.w, aB.y, 1.f);
        r0 *= fmaf(Ev.x, bA.x, 1.f);
        r1 *= fmaf(Ev.y, bA.y, 1.f);
        r2 *= fmaf(Ev.z, bB.x, 1.f);
        r3 *= fmaf(Ev.w, bB.y, 1.f);
    }
    float ek0 = ebf0 * sqrtf((p0 * p1) * (p2 * p3));
    float ek1 = ebf1 * sqrtf((r0 * r1) * (r2 * r3));

    // gumbel-max in exp domain: argmax(l+g) == argmax(ek / z); keys > 0
    float z0 = -logf(u0 + 1e-9f) + 1e-9f;
    float z1 = -logf(u1 + 1e-9f) + 1e-9f;
    float key0 = ek0 / z0;
    float key1 = ek1 / z1;

    float key; int ki;
    if (key0 >= key1) { key = key0; ki = k0; } else { key = key1; ki = k1; }

    // warp sum (5 shfl) + warp argmax (redux + ballot + 1 shfl)
    float s = ek0 + ek1;
    #pragma unroll
    for (int off = 16; off; off >>= 1) s += __shfl_xor_sync(0xffffffffu, s, off);
    unsigned km   = fmono(key);
    unsigned wmax = __reduce_max_sync(0xffffffffu, km);
    unsigned ball = __ballot_sync(0xffffffffu, km == wmax);
    int      wki  = __shfl_sync(0xffffffffu, ki, __ffs(ball) - 1);
    if (lane == 0) { sredf[w] = s; sredk[w] = make_uint2(wmax, (unsigned)wki); }
    __syncthreads();                           // B2

    // ---- every thread combines 4 warp partials via broadcast LDS ----
    float Sf;
    int   kstar;
    {
        Sf = (sredf[0] + sredf[1]) + (sredf[2] + sredf[3]);
        uint2 c0 = sredk[0], c1 = sredk[1], c2 = sredk[2], c3 = sredk[3];
        uint2 mA = (c1.x > c0.x || (c1.x == c0.x && c1.y < c0.y)) ? c1 : c0;
        uint2 mB = (c3.x > c2.x || (c3.x == c2.x && c3.y < c2.y)) ? c3 : c2;
        uint2 mm = (mB.x > mA.x || (mB.x == mA.x && mB.y < mA.y)) ? mB : mA;
        kstar = (int)mm.y;
    }

    // ---- warp 0: rank-1 update E' = E * e^{delta_kstar W[kstar,:]}, ratio R ----
    if (w == 0) {
        float xks = xs[kstar];
        const float2* t2 = (const float2*)((xks == 0.0f) ? g_ewp : g_ewm);
        float2 pr = __ldg(&t2[(lane >> 1) * DD + kstar]);
        float mj  = (lane & 1) ? pr.y : pr.x;
        float E2  = E * mj;
        sE2[lane] = E2;
        float r = (1.f + E2) / (1.f + E);
        #pragma unroll
        for (int off = 16; off; off >>= 1) r *= __shfl_xor_sync(0xffffffffu, r, off);
        if (lane == 0) sRt = r;
    }
    __syncthreads();                           // B3

    // ---- reverse pass at x_delta: tables flip only for the kstar dim ----
    const float2* t0r = (k0 == kstar) ? ((xk0 == 0.0f) ? (const float2*)g_ewm : (const float2*)g_ewp) : t0;
    const float2* t1r = (k1 == kstar) ? ((xk1 == 0.0f) ? (const float2*)g_ewm : (const float2*)g_ewp) : t1;
    const float ebr0 = (k0 == kstar) ? ((xk0 == 0.0f) ? eb0.y : eb0.x) : ebf0;
    const float ebr1 = (k1 == kstar) ? ((xk1 == 0.0f) ? eb1.y : eb1.x) : ebf1;
    const float4* sE42 = (const float4*)sE2;

    float q0 = 1.f, q1 = 1.f, q2 = 1.f, q3 = 1.f;
    float v0 = 1.f, v1 = 1.f, v2 = 1.f, v3 = 1.f;
    #pragma unroll
    for (int jp = 0; jp < 16; jp += 2) {
        float4 Ev = sE42[jp >> 1];
        float2 aA = __ldg(&t0r[jp * DD + k0]);
        float2 aB = __ldg(&t0r[(jp + 1) * DD + k0]);
        float2 bA = __ldg(&t1r[jp * DD + k1]);
        float2 bB = __ldg(&t1r[(jp + 1) * DD + k1]);
        q0 *= fmaf(Ev.x, aA.x, 1.f);
        q1 *= fmaf(Ev.y, aA.y, 1.f);
        q2 *= fmaf(Ev.z, aB.x, 1.f);
        q3 *= fmaf(Ev.w, aB.y, 1.f);
        v0 *= fmaf(Ev.x, bA.x, 1.f);
        v1 *= fmaf(Ev.y, bA.y, 1.f);
        v2 *= fmaf(Ev.z, bB.x, 1.f);
        v3 *= fmaf(Ev.w, bB.y, 1.f);
    }
    float er0 = ebr0 * sqrtf((q0 * q1) * (q2 * q3));
    float er1 = ebr1 * sqrtf((v0 * v1) * (v2 * v3));

    float s2 = er0 + er1;
    #pragma unroll
    for (int off = 16; off; off >>= 1) s2 += __shfl_xor_sync(0xffffffffu, s2, off);
    if (lane == 0) sredf[w] = s2;
    __syncthreads();                           // B4

    float Sr = (sredf[0] + sredf[1]) + (sredf[2] + sredf[3]);

    // ---- accept: Zf/Zr = sqrt(R) * Sf / Sr > u ----
    bool accv = sqrtf(sRt) * Sf > au * Sr;
    out[row * DD + k0] = (k0 == kstar && accv) ? (1.f - xk0) : xk0;
    out[row * DD + k1] = (k1 == kstar && accv) ? (1.f - xk1) : xk1;
}

extern "C" void kernel_launch(void* const* d_in, const int* in_sizes, int n_in,
                              void* d_out, int out_size) {
    const float* x   = (const float*)d_in[0];
    const float* W   = (const float*)d_in[1];
    const float* b   = (const float*)d_in[2];
    const float* c   = (const float*)d_in[3];
    const float* gum = (const float*)d_in[4];
    const float* acc = (const float*)d_in[5];
    float* out = (float*)d_out;

    prep_kernel<<<8 + BB / 8, 256>>>(x, W, b, c);
    gwg_kernel<<<BB, 128>>>(x, gum, acc, out);
}

// round 7
// speedup vs baseline: 1.3846x; 1.3846x over previous
#include <cuda_runtime.h>

#define BB 1024
#define DD 256
#define HH 32

// exp(+W)/exp(-W), interleaved by j-pair: float2 element [pr*DD + d] holds
// (exp(s*W[d, 2*pr]), exp(s*W[d, 2*pr+1])) -> one coalesced LDG.64 per 2 factors.
__device__ float  g_ewp[HH * DD];
__device__ float  g_ewm[HH * DD];
__device__ float2 g_eb[DD];          // (exp(+b/2), exp(-b/2))
__device__ float  g_E[BB * HH];      // E_j(row) = exp((x@W)_j + c_j)

// Prep: blocks 0..7 build tables; blocks 8..8+BB-1 compute E, one block per row.
__global__ __launch_bounds__(256) void prep_kernel(
    const float* __restrict__ x,
    const float* __restrict__ W,
    const float* __restrict__ b,
    const float* __restrict__ c)
{
    const int bid = blockIdx.x;
    const int tid = threadIdx.x;
    if (bid < 8) {
        for (int t = bid * 256 + tid; t < DD * HH; t += 8 * 256) {
            int d = t >> 5;
            int j = t & 31;
            float w = W[t];
            int idx = (j >> 1) * (DD * 2) + d * 2 + (j & 1);
            g_ewp[idx] = expf(w);
            g_ewm[idx] = expf(-w);
        }
        int t = bid * 256 + tid;
        if (t < DD) {
            float bv = b[t];
            g_eb[t] = make_float2(expf(0.5f * bv), expf(-0.5f * bv));
        }
        return;
    }

    // ---- E rows: block per row; warp w covers d in [32w,32w+32), lane = j ----
    __shared__ float ap[8][32];
    const int row  = bid - 8;
    const int w    = tid >> 5;
    const int lane = tid & 31;

    unsigned m = __ballot_sync(0xffffffffu, x[row * DD + w * 32 + lane] != 0.0f);
    const float* Wb = W + (w * 32) * HH + lane;
    float pa = 0.f, pb = 0.f;
    #pragma unroll
    for (int i = 0; i < 32; i += 2) {
        if (m & (1u << i))       pa += Wb[i * HH];
        if (m & (1u << (i + 1))) pb += Wb[(i + 1) * HH];
    }
    ap[w][lane] = pa + pb;
    __syncthreads();

    if (w == 0) {
        float a = c[lane];
        #pragma unroll
        for (int ww = 0; ww < 8; ++ww) a += ap[ww][lane];
        g_E[row * HH + lane] = expf(a);
    }
}

__device__ __forceinline__ unsigned fmono(float f) {
    unsigned u = __float_as_uint(f);
    return (u & 0x80000000u) ? ~u : (u | 0x80000000u);
}

__global__ __launch_bounds__(128, 8) void gwg_kernel(
    const float* __restrict__ x,
    const float* __restrict__ gum,
    const float* __restrict__ acc,
    float* __restrict__ out)
{
    __shared__ float xs[DD];
    __shared__ __align__(16) float sEf[HH];   // E_j
    __shared__ __align__(16) float sE2[HH];   // E'_j after rank-1 update
    __shared__ float sredf[4];
    __shared__ uint2 sredk[4];                // (fmono(key), idx) per warp
    __shared__ float sRt;

    const int row  = blockIdx.x;
    const int tid  = threadIdx.x;
    const int w    = tid >> 5;
    const int lane = tid & 31;
    const int k0   = tid;          // dims tid and tid+128
    const int k1   = tid + 128;

    float  xk0 = x[row * DD + k0];
    float  xk1 = x[row * DD + k1];
    float2 eb0 = g_eb[k0];
    float2 eb1 = g_eb[k1];
    float  u0  = gum[row * DD + k0];
    float  u1  = gum[row * DD + k1];
    float  au  = acc[row];
    xs[k0] = xk0;
    xs[k1] = xk1;

    float E = 0.f;                             // warp 0 keeps its E_lane
    if (w == 0) { E = g_E[row * HH + lane]; sEf[lane] = E; }
    __syncthreads();                           // B1

    // ---- forward: p~_k = prod_j (1 + E_j e^{delta_k w_kj});  ek = eb * sqrt ----
    const float2* t0 = (const float2*)((xk0 == 0.0f) ? g_ewp : g_ewm);
    const float2* t1 = (const float2*)((xk1 == 0.0f) ? g_ewp : g_ewm);
    const float ebf0 = (xk0 == 0.0f) ? eb0.x : eb0.y;
    const float ebf1 = (xk1 == 0.0f) ? eb1.x : eb1.y;
    const float4* sE4f = (const float4*)sEf;

    float p0 = 1.f, p1 = 1.f, p2 = 1.f, p3 = 1.f;
    float r0 = 1.f, r1 = 1.f, r2 = 1.f, r3 = 1.f;
    #pragma unroll
    for (int jp = 0; jp < 16; jp += 2) {
        float4 Ev = sE4f[jp >> 1];
        float2 aA = __ldg(&t0[jp * DD + k0]);
        float2 aB = __ldg(&t0[(jp + 1) * DD + k0]);
        float2 bA = __ldg(&t1[jp * DD + k1]);
        float2 bB = __ldg(&t1[(jp + 1) * DD + k1]);
        p0 *= fmaf(Ev.x, aA.x, 1.f);
        p1 *= fmaf(Ev.y, aA.y, 1.f);
        p2 *= fmaf(Ev.z, aB.x, 1.f);
        p3 *= fmaf(Ev.w, aB.y, 1.f);
        r0 *= fmaf(Ev.x, bA.x, 1.f);
        r1 *= fmaf(Ev.y, bA.y, 1.f);
        r2 *= fmaf(Ev.z, bB.x, 1.f);
        r3 *= fmaf(Ev.w, bB.y, 1.f);
    }
    float ek0 = ebf0 * sqrtf((p0 * p1) * (p2 * p3));
    float ek1 = ebf1 * sqrtf((r0 * r1) * (r2 * r3));

    // gumbel-max in exp domain: argmax(l+g) == argmax(ek / z); keys > 0
    float z0 = -logf(u0 + 1e-9f) + 1e-9f;
    float z1 = -logf(u1 + 1e-9f) + 1e-9f;
    float key0 = ek0 / z0;
    float key1 = ek1 / z1;

    float key; int ki;
    if (key0 >= key1) { key = key0; ki = k0; } else { key = key1; ki = k1; }

    // warp sum (5 shfl) + warp argmax (redux + ballot + 1 shfl)
    float s = ek0 + ek1;
    #pragma unroll
    for (int off = 16; off; off >>= 1) s += __shfl_xor_sync(0xffffffffu, s, off);
    unsigned km   = fmono(key);
    unsigned wmax = __reduce_max_sync(0xffffffffu, km);
    unsigned ball = __ballot_sync(0xffffffffu, km == wmax);
    int      wki  = __shfl_sync(0xffffffffu, ki, __ffs(ball) - 1);
    if (lane == 0) { sredf[w] = s; sredk[w] = make_uint2(wmax, (unsigned)wki); }
    __syncthreads();                           // B2

    // ---- every thread combines 4 warp partials via broadcast LDS ----
    float Sf;
    int   kstar;
    {
        Sf = (sredf[0] + sredf[1]) + (sredf[2] + sredf[3]);
        uint2 c0 = sredk[0], c1 = sredk[1], c2 = sredk[2], c3 = sredk[3];
        uint2 mA = (c1.x > c0.x || (c1.x == c0.x && c1.y < c0.y)) ? c1 : c0;
        uint2 mB = (c3.x > c2.x || (c3.x == c2.x && c3.y < c2.y)) ? c3 : c2;
        uint2 mm = (mB.x > mA.x || (mB.x == mA.x && mB.y < mA.y)) ? mB : mA;
        kstar = (int)mm.y;
    }

    // ---- warp 0: rank-1 update E' = E * e^{delta_kstar W[kstar,:]}, ratio R ----
    if (w == 0) {
        float xks = xs[kstar];
        const float2* t2 = (const float2*)((xks == 0.0f) ? g_ewp : g_ewm);
        float2 pr = __ldg(&t2[(lane >> 1) * DD + kstar]);
        float mj  = (lane & 1) ? pr.y : pr.x;
        float E2  = E * mj;
        sE2[lane] = E2;
        float r = (1.f + E2) / (1.f + E);
        #pragma unroll
        for (int off = 16; off; off >>= 1) r *= __shfl_xor_sync(0xffffffffu, r, off);
        if (lane == 0) sRt = r;
    }
    __syncthreads();                           // B3

    // ---- reverse pass at x_delta: tables flip only for the kstar dim ----
    const float2* t0r = (k0 == kstar) ? ((xk0 == 0.0f) ? (const float2*)g_ewm : (const float2*)g_ewp) : t0;
    const float2* t1r = (k1 == kstar) ? ((xk1 == 0.0f) ? (const float2*)g_ewm : (const float2*)g_ewp) : t1;
    const float ebr0 = (k0 == kstar) ? ((xk0 == 0.0f) ? eb0.y : eb0.x) : ebf0;
    const float ebr1 = (k1 == kstar) ? ((xk1 == 0.0f) ? eb1.y : eb1.x) : ebf1;
    const float4* sE42 = (const float4*)sE2;

    float q0 = 1.f, q1 = 1.f, q2 = 1.f, q3 = 1.f;
    float v0 = 1.f, v1 = 1.f, v2 = 1.f, v3 = 1.f;
    #pragma unroll
    for (int jp = 0; jp < 16; jp += 2) {
        float4 Ev = sE42[jp >> 1];
        float2 aA = __ldg(&t0r[jp * DD + k0]);
        float2 aB = __ldg(&t0r[(jp + 1) * DD + k0]);
        float2 bA = __ldg(&t1r[jp * DD + k1]);
        float2 bB = __ldg(&t1r[(jp + 1) * DD + k1]);
        q0 *= fmaf(Ev.x, aA.x, 1.f);
        q1 *= fmaf(Ev.y, aA.y, 1.f);
        q2 *= fmaf(Ev.z, aB.x, 1.f);
        q3 *= fmaf(Ev.w, aB.y, 1.f);
        v0 *= fmaf(Ev.x, bA.x, 1.f);
        v1 *= fmaf(Ev.y, bA.y, 1.f);
        v2 *= fmaf(Ev.z, bB.x, 1.f);
        v3 *= fmaf(Ev.w, bB.y, 1.f);
    }
    float er0 = ebr0 * sqrtf((q0 * q1) * (q2 * q3));
    float er1 = ebr1 * sqrtf((v0 * v1) * (v2 * v3));

    float s2 = er0 + er1;
    #pragma unroll
    for (int off = 16; off; off >>= 1) s2 += __shfl_xor_sync(0xffffffffu, s2, off);
    if (lane == 0) sredf[w] = s2;
    __syncthreads();                           // B4

    float Sr = (sredf[0] + sredf[1]) + (sredf[2] + sredf[3]);

    // ---- accept: Zf/Zr = sqrt(R) * Sf / Sr > u ----
    bool accv = sqrtf(sRt) * Sf > au * Sr;
    out[row * DD + k0] = (k0 == kstar && accv) ? (1.f - xk0) : xk0;
    out[row * DD + k1] = (k1 == kstar && accv) ? (1.f - xk1) : xk1;
}

extern "C" void kernel_launch(void* const* d_in, const int* in_sizes, int n_in,
                              void* d_out, int out_size) {
    const float* x   = (const float*)d_in[0];
    const float* W   = (const float*)d_in[1];
    const float* b   = (const float*)d_in[2];
    const float* c   = (const float*)d_in[3];
    const float* gum = (const float*)d_in[4];
    const float* acc = (const float*)d_in[5];
    float* out = (float*)d_out;

    prep_kernel<<<8 + BB, 256>>>(x, W, b, c);
    gwg_kernel<<<BB, 128>>>(x, gum, acc, out);
}

// round 8
// speedup vs baseline: 1.4436x; 1.0426x over previous
#include <cuda_runtime.h>

#define BB 1024
#define DD 256
#define HH 32

// exp(+W)/exp(-W), interleaved by j-pair: float2 element [pr*DD + d] holds
// (exp(s*W[d, 2*pr]), exp(s*W[d, 2*pr+1])) -> one coalesced LDG.64 per 2 factors.
__device__ float  g_ewp[HH * DD];
__device__ float  g_ewm[HH * DD];
__device__ float2 g_eb[DD];          // (exp(+b/2), exp(-b/2))
__device__ float  g_E[BB * HH];      // E_j(row) = exp((x@W)_j + c_j)

// Prep: blocks 0..7 build tables; blocks 8..8+BB/8-1 compute E, 8 rows per block.
__global__ __launch_bounds__(256) void prep_kernel(
    const float* __restrict__ x,
    const float* __restrict__ W,
    const float* __restrict__ b,
    const float* __restrict__ c)
{
    const int bid = blockIdx.x;
    const int tid = threadIdx.x;
    if (bid < 8) {
        for (int t = bid * 256 + tid; t < DD * HH; t += 8 * 256) {
            int d = t >> 5;
            int j = t & 31;
            float w = W[t];
            int idx = (j >> 1) * (DD * 2) + d * 2 + (j & 1);
            g_ewp[idx] = expf(w);
            g_ewm[idx] = expf(-w);
        }
        int t = bid * 256 + tid;
        if (t < DD) {
            float bv = b[t];
            g_eb[t] = make_float2(expf(0.5f * bv), expf(-0.5f * bv));
        }
        return;
    }

    // ---- E for 8 rows: warp w covers d in [32w,32w+32), lane = j.
    //      Each W value is loaded once and reused across 8 rows (8 masks). ----
    __shared__ float ap[8][8][32];           // [warp][row][j]
    const int row0 = (bid - 8) * 8;
    const int w    = tid >> 5;
    const int lane = tid & 31;

    unsigned m[8];
    #pragma unroll
    for (int r = 0; r < 8; ++r)
        m[r] = __ballot_sync(0xffffffffu, x[(row0 + r) * DD + w * 32 + lane] != 0.0f);

    const float* Wb = W + (w * 32) * HH + lane;
    float acc[8] = {0.f, 0.f, 0.f, 0.f, 0.f, 0.f, 0.f, 0.f};
    #pragma unroll
    for (int i = 0; i < 32; ++i) {
        float wv = Wb[i * HH];
        #pragma unroll
        for (int r = 0; r < 8; ++r)
            if (m[r] & (1u << i)) acc[r] += wv;
    }
    #pragma unroll
    for (int r = 0; r < 8; ++r) ap[w][r][lane] = acc[r];
    __syncthreads();

    // warp w finishes row (row0 + w)
    float a = c[lane];
    #pragma unroll
    for (int ww = 0; ww < 8; ++ww) a += ap[ww][w][lane];
    g_E[(row0 + w) * HH + lane] = expf(a);
}

__device__ __forceinline__ unsigned fmono(float f) {
    unsigned u = __float_as_uint(f);
    return (u & 0x80000000u) ? ~u : (u | 0x80000000u);
}

__global__ __launch_bounds__(128, 8) void gwg_kernel(
    const float* __restrict__ x,
    const float* __restrict__ gum,
    const float* __restrict__ acc,
    float* __restrict__ out)
{
    __shared__ float xs[DD];
    __shared__ __align__(16) float sEf[HH];   // E_j
    __shared__ __align__(16) float sE2[HH];   // E'_j after rank-1 update
    __shared__ float sredf[4];
    __shared__ uint2 sredk[4];                // (fmono(key), idx) per warp
    __shared__ float sRt;

    const int row  = blockIdx.x;
    const int tid  = threadIdx.x;
    const int w    = tid >> 5;
    const int lane = tid & 31;
    const int k0   = tid;          // dims tid and tid+128
    const int k1   = tid + 128;

    float  xk0 = x[row * DD + k0];
    float  xk1 = x[row * DD + k1];
    float2 eb0 = g_eb[k0];
    float2 eb1 = g_eb[k1];
    float  u0  = gum[row * DD + k0];
    float  u1  = gum[row * DD + k1];
    float  au  = acc[row];
    xs[k0] = xk0;
    xs[k1] = xk1;

    float E = 0.f;                             // warp 0 keeps its E_lane
    if (w == 0) { E = g_E[row * HH + lane]; sEf[lane] = E; }
    __syncthreads();                           // B1

    // ---- forward: p~_k = prod_j (1 + E_j e^{delta_k w_kj});  ek = eb * sqrt ----
    const float2* t0 = (const float2*)((xk0 == 0.0f) ? g_ewp : g_ewm);
    const float2* t1 = (const float2*)((xk1 == 0.0f) ? g_ewp : g_ewm);
    const float ebf0 = (xk0 == 0.0f) ? eb0.x : eb0.y;
    const float ebf1 = (xk1 == 0.0f) ? eb1.x : eb1.y;
    const float4* sE4f = (const float4*)sEf;

    float p0 = 1.f, p1 = 1.f, p2 = 1.f, p3 = 1.f;
    float r0 = 1.f, r1 = 1.f, r2 = 1.f, r3 = 1.f;
    #pragma unroll
    for (int jp = 0; jp < 16; jp += 2) {
        float4 Ev = sE4f[jp >> 1];
        float2 aA = __ldg(&t0[jp * DD + k0]);
        float2 aB = __ldg(&t0[(jp + 1) * DD + k0]);
        float2 bA = __ldg(&t1[jp * DD + k1]);
        float2 bB = __ldg(&t1[(jp + 1) * DD + k1]);
        p0 *= fmaf(Ev.x, aA.x, 1.f);
        p1 *= fmaf(Ev.y, aA.y, 1.f);
        p2 *= fmaf(Ev.z, aB.x, 1.f);
        p3 *= fmaf(Ev.w, aB.y, 1.f);
        r0 *= fmaf(Ev.x, bA.x, 1.f);
        r1 *= fmaf(Ev.y, bA.y, 1.f);
        r2 *= fmaf(Ev.z, bB.x, 1.f);
        r3 *= fmaf(Ev.w, bB.y, 1.f);
    }
    float ek0 = ebf0 * sqrtf((p0 * p1) * (p2 * p3));
    float ek1 = ebf1 * sqrtf((r0 * r1) * (r2 * r3));

    // gumbel-max in exp domain: argmax(l+g) == argmax(ek / z); keys > 0
    float z0 = -logf(u0 + 1e-9f) + 1e-9f;
    float z1 = -logf(u1 + 1e-9f) + 1e-9f;
    float key0 = ek0 / z0;
    float key1 = ek1 / z1;

    float key; int ki;
    if (key0 >= key1) { key = key0; ki = k0; } else { key = key1; ki = k1; }

    // warp sum (5 shfl) + warp argmax (redux + ballot + 1 shfl)
    float s = ek0 + ek1;
    #pragma unroll
    for (int off = 16; off; off >>= 1) s += __shfl_xor_sync(0xffffffffu, s, off);
    unsigned km   = fmono(key);
    unsigned wmax = __reduce_max_sync(0xffffffffu, km);
    unsigned ball = __ballot_sync(0xffffffffu, km == wmax);
    int      wki  = __shfl_sync(0xffffffffu, ki, __ffs(ball) - 1);
    if (lane == 0) { sredf[w] = s; sredk[w] = make_uint2(wmax, (unsigned)wki); }
    __syncthreads();                           // B2

    // ---- every thread combines 4 warp partials via broadcast LDS ----
    float Sf;
    int   kstar;
    {
        Sf = (sredf[0] + sredf[1]) + (sredf[2] + sredf[3]);
        uint2 c0 = sredk[0], c1 = sredk[1], c2 = sredk[2], c3 = sredk[3];
        uint2 mA = (c1.x > c0.x || (c1.x == c0.x && c1.y < c0.y)) ? c1 : c0;
        uint2 mB = (c3.x > c2.x || (c3.x == c2.x && c3.y < c2.y)) ? c3 : c2;
        uint2 mm = (mB.x > mA.x || (mB.x == mA.x && mB.y < mA.y)) ? mB : mA;
        kstar = (int)mm.y;
    }

    // ---- warp 0: rank-1 update E' = E * e^{delta_kstar W[kstar,:]}, ratio R ----
    if (w == 0) {
        float xks = xs[kstar];
        const float2* t2 = (const float2*)((xks == 0.0f) ? g_ewp : g_ewm);
        float2 pr = __ldg(&t2[(lane >> 1) * DD + kstar]);
        float mj  = (lane & 1) ? pr.y : pr.x;
        float E2  = E * mj;
        sE2[lane] = E2;
        float r = (1.f + E2) / (1.f + E);
        #pragma unroll
        for (int off = 16; off; off >>= 1) r *= __shfl_xor_sync(0xffffffffu, r, off);
        if (lane == 0) sRt = r;
    }
    __syncthreads();                           // B3

    // ---- reverse pass at x_delta: tables flip only for the kstar dim ----
    const float2* t0r = (k0 == kstar) ? ((xk0 == 0.0f) ? (const float2*)g_ewm : (const float2*)g_ewp) : t0;
    const float2* t1r = (k1 == kstar) ? ((xk1 == 0.0f) ? (const float2*)g_ewm : (const float2*)g_ewp) : t1;
    const float ebr0 = (k0 == kstar) ? ((xk0 == 0.0f) ? eb0.y : eb0.x) : ebf0;
    const float ebr1 = (k1 == kstar) ? ((xk1 == 0.0f) ? eb1.y : eb1.x) : ebf1;
    const float4* sE42 = (const float4*)sE2;

    float q0 = 1.f, q1 = 1.f, q2 = 1.f, q3 = 1.f;
    float v0 = 1.f, v1 = 1.f, v2 = 1.f, v3 = 1.f;
    #pragma unroll
    for (int jp = 0; jp < 16; jp += 2) {
        float4 Ev = sE42[jp >> 1];
        float2 aA = __ldg(&t0r[jp * DD + k0]);
        float2 aB = __ldg(&t0r[(jp + 1) * DD + k0]);
        float2 bA = __ldg(&t1r[jp * DD + k1]);
        float2 bB = __ldg(&t1r[(jp + 1) * DD + k1]);
        q0 *= fmaf(Ev.x, aA.x, 1.f);
        q1 *= fmaf(Ev.y, aA.y, 1.f);
        q2 *= fmaf(Ev.z, aB.x, 1.f);
        q3 *= fmaf(Ev.w, aB.y, 1.f);
        v0 *= fmaf(Ev.x, bA.x, 1.f);
        v1 *= fmaf(Ev.y, bA.y, 1.f);
        v2 *= fmaf(Ev.z, bB.x, 1.f);
        v3 *= fmaf(Ev.w, bB.y, 1.f);
    }
    float er0 = ebr0 * sqrtf((q0 * q1) * (q2 * q3));
    float er1 = ebr1 * sqrtf((v0 * v1) * (v2 * v3));

    float s2 = er0 + er1;
    #pragma unroll
    for (int off = 16; off; off >>= 1) s2 += __shfl_xor_sync(0xffffffffu, s2, off);
    if (lane == 0) sredf[w] = s2;
    __syncthreads();                           // B4

    float Sr = (sredf[0] + sredf[1]) + (sredf[2] + sredf[3]);

    // ---- accept: Zf/Zr = sqrt(R) * Sf / Sr > u ----
    bool accv = sqrtf(sRt) * Sf > au * Sr;
    out[row * DD + k0] = (k0 == kstar && accv) ? (1.f - xk0) : xk0;
    out[row * DD + k1] = (k1 == kstar && accv) ? (1.f - xk1) : xk1;
}

extern "C" void kernel_launch(void* const* d_in, const int* in_sizes, int n_in,
                              void* d_out, int out_size) {
    const float* x   = (const float*)d_in[0];
    const float* W   = (const float*)d_in[1];
    const float* b   = (const float*)d_in[2];
    const float* c   = (const float*)d_in[3];
    const float* gum = (const float*)d_in[4];
    const float* acc = (const float*)d_in[5];
    float* out = (float*)d_out;

    prep_kernel<<<8 + BB / 8, 256>>>(x, W, b, c);
    gwg_kernel<<<BB, 128>>>(x, gum, acc, out);
}